// round 1
// baseline (speedup 1.0000x reference)
#include <cuda_runtime.h>
#include <math.h>

// Problem constants
#define S_LEN 256
#define B_SZ  32
#define E_DIM 300
#define H_DIM 2400
#define N3H   (3 * H_DIM)          // 7200
#define M_ROWS (S_LEN * B_SZ)      // 8192

// Scratch (allocation-free rule: __device__ globals)
__device__ float g_gates[(size_t)M_ROWS * N3H];   // [S*B, 3H] post-activation gates
__device__ float g_x[(size_t)M_ROWS * H_DIM];     // [S*B, H]  hidden seq (next layer input)
__device__ float g_acc[B_SZ * H_DIM];             // running sum of final cells

// ---------------------------------------------------------------------------
// Activations
// ---------------------------------------------------------------------------
__device__ __forceinline__ float sigmoid_f(float x) {
    return __fdividef(1.0f, 1.0f + __expf(-x));
}

// ---------------------------------------------------------------------------
// GEMM: C[m,n] = act( sum_k A[m,k]*W[n,k] + bias[n] )  -> g_gates
//   A: [M_ROWS, K] row-major, W: [N3H, K] row-major (nn.Linear layout)
//   act: tanh for n < H, sigmoid otherwise.
// 128x128 tile, BK=8, 256 threads, 8x8 per thread, packed fma.rn.f32x2.
// ---------------------------------------------------------------------------
__global__ __launch_bounds__(256) void gemm_gates_kernel(
    const float* __restrict__ Aext,
    const float* __restrict__ W,
    const float* __restrict__ bias,
    int K, int use_internal_x)
{
    const float* __restrict__ A = use_internal_x ? g_x : Aext;

    __shared__ __align__(16) float As[8][128];
    __shared__ __align__(16) float Bs[8][128];

    const int tid = threadIdx.x;
    const int tx  = tid & 15;   // 0..15 -> n sub-tile
    const int ty  = tid >> 4;   // 0..15 -> m sub-tile
    const int m0  = blockIdx.y * 128;
    const int n0  = blockIdx.x * 128;

    // Load mapping: one float4 per thread per operand per tile
    const int lrow = tid >> 1;          // 0..127
    const int lkc  = (tid & 1) * 4;     // 0 or 4

    const float* Aptr = A + (size_t)(m0 + lrow) * K + lkc;
    const float* Wptr = W + (size_t)(n0 + lrow) * K + lkc;
    const bool nvalid = (n0 + lrow) < N3H;   // M_ROWS % 128 == 0, only N needs a guard

    // Packed accumulators: acc[i][j] holds columns (tx*8 + 2j, tx*8 + 2j + 1)
    unsigned long long acc[8][4];
#pragma unroll
    for (int i = 0; i < 8; i++)
#pragma unroll
        for (int j = 0; j < 4; j++) acc[i][j] = 0ull;

    const int nt = (K + 7) / 8;

    // Prefetch tile 0 into registers
    float4 av, bv;
    {
        const bool kv = (lkc < K);  // K % 4 == 0 so whole float4 is valid iff start valid
        av = kv ? *(const float4*)(Aptr) : make_float4(0.f, 0.f, 0.f, 0.f);
        bv = (kv && nvalid) ? *(const float4*)(Wptr) : make_float4(0.f, 0.f, 0.f, 0.f);
    }

    for (int t = 0; t < nt; ++t) {
        // Stage prefetched registers into SMEM (transposed: [k][row])
        As[lkc + 0][lrow] = av.x;
        As[lkc + 1][lrow] = av.y;
        As[lkc + 2][lrow] = av.z;
        As[lkc + 3][lrow] = av.w;
        Bs[lkc + 0][lrow] = bv.x;
        Bs[lkc + 1][lrow] = bv.y;
        Bs[lkc + 2][lrow] = bv.z;
        Bs[lkc + 3][lrow] = bv.w;
        __syncthreads();

        // Prefetch next tile (global, no smem touch)
        if (t + 1 < nt) {
            const int kg = (t + 1) * 8 + lkc;
            const bool kv = (kg < K);
            const float* ap = Aptr + (size_t)(t + 1) * 8;
            const float* wp = Wptr + (size_t)(t + 1) * 8;
            av = kv ? *(const float4*)(ap) : make_float4(0.f, 0.f, 0.f, 0.f);
            bv = (kv && nvalid) ? *(const float4*)(wp) : make_float4(0.f, 0.f, 0.f, 0.f);
        }

        // Compute on current tile
#pragma unroll
        for (int kk = 0; kk < 8; ++kk) {
            const float4 a0 = *(const float4*)&As[kk][ty * 8];
            const float4 a1 = *(const float4*)&As[kk][ty * 8 + 4];
            const unsigned long long b0 = *(const unsigned long long*)&Bs[kk][tx * 8 + 0];
            const unsigned long long b1 = *(const unsigned long long*)&Bs[kk][tx * 8 + 2];
            const unsigned long long b2 = *(const unsigned long long*)&Bs[kk][tx * 8 + 4];
            const unsigned long long b3 = *(const unsigned long long*)&Bs[kk][tx * 8 + 6];
            const float avv[8] = {a0.x, a0.y, a0.z, a0.w, a1.x, a1.y, a1.z, a1.w};
#pragma unroll
            for (int i = 0; i < 8; i++) {
                unsigned long long a2;
                asm("mov.b64 %0, {%1, %1};" : "=l"(a2) : "f"(avv[i]));
                asm("fma.rn.f32x2 %0, %1, %2, %0;" : "+l"(acc[i][0]) : "l"(a2), "l"(b0));
                asm("fma.rn.f32x2 %0, %1, %2, %0;" : "+l"(acc[i][1]) : "l"(a2), "l"(b1));
                asm("fma.rn.f32x2 %0, %1, %2, %0;" : "+l"(acc[i][2]) : "l"(a2), "l"(b2));
                asm("fma.rn.f32x2 %0, %1, %2, %0;" : "+l"(acc[i][3]) : "l"(a2), "l"(b3));
            }
        }
        __syncthreads();
    }

    // Epilogue: bias + activation + store to g_gates
#pragma unroll
    for (int i = 0; i < 8; i++) {
        const int m = m0 + ty * 8 + i;
        float* crow = g_gates + (size_t)m * N3H;
#pragma unroll
        for (int j = 0; j < 4; j++) {
            float lo, hi;
            asm("mov.b64 {%0, %1}, %2;" : "=f"(lo), "=f"(hi) : "l"(acc[i][j]));
            const int n = n0 + tx * 8 + j * 2;
            if (n < N3H) {
                float y = lo + bias[n];
                crow[n] = (n < H_DIM) ? tanhf(y) : sigmoid_f(y);
            }
            if (n + 1 < N3H) {
                float y = hi + bias[n + 1];
                crow[n + 1] = ((n + 1) < H_DIM) ? tanhf(y) : sigmoid_f(y);
            }
        }
    }
}

// ---------------------------------------------------------------------------
// fo-pool scan over S. One thread per (b,h) lane.
//   mode 0: g_acc  = c_last, write hidden seq to g_x
//   mode 1: g_acc += c_last, write hidden seq to g_x
//   mode 2: out    = (g_acc + c_last) / sent_len[b]   (no hidden write)
// ---------------------------------------------------------------------------
__global__ void scan_kernel(int mode, const int* __restrict__ sent_len,
                            float* __restrict__ out)
{
    const int idx = blockIdx.x * blockDim.x + threadIdx.x;
    if (idx >= B_SZ * H_DIM) return;
    const int b = idx / H_DIM;
    const int h = idx - b * H_DIM;

    const size_t stride  = (size_t)B_SZ * N3H;
    const size_t xstride = (size_t)B_SZ * H_DIM;
    size_t base  = (size_t)b * N3H + h;
    size_t xbase = (size_t)b * H_DIM + h;

    float c = 0.0f;
    if (mode != 2) {
#pragma unroll 4
        for (int s = 0; s < S_LEN; ++s) {
            const float z = g_gates[base];
            const float f = g_gates[base + H_DIM];
            const float o = g_gates[base + 2 * H_DIM];
            c = fmaf(f, c - z, z);          // f*c + (1-f)*z
            g_x[xbase] = o * c;
            base  += stride;
            xbase += xstride;
        }
    } else {
#pragma unroll 4
        for (int s = 0; s < S_LEN; ++s) {
            const float z = g_gates[base];
            const float f = g_gates[base + H_DIM];
            c = fmaf(f, c - z, z);
            base += stride;
        }
    }

    if (mode == 0)      g_acc[idx] = c;
    else if (mode == 1) g_acc[idx] += c;
    else                out[idx] = (g_acc[idx] + c) / (float)sent_len[b];
}

// ---------------------------------------------------------------------------
extern "C" void kernel_launch(void* const* d_in, const int* in_sizes, int n_in,
                              void* d_out, int out_size)
{
    const float* sent     = (const float*)d_in[0];
    const int*   sent_len = (const int*)  d_in[1];
    const float* W1 = (const float*)d_in[2];
    const float* b1 = (const float*)d_in[3];
    const float* W2 = (const float*)d_in[4];
    const float* b2 = (const float*)d_in[5];
    const float* W3 = (const float*)d_in[6];
    const float* b3 = (const float*)d_in[7];
    float* out = (float*)d_out;

    const dim3 gblk(256);
    const dim3 ggrid((N3H + 127) / 128, M_ROWS / 128);   // 57 x 64
    const int sthreads = 256;
    const int sblocks  = (B_SZ * H_DIM + sthreads - 1) / sthreads;  // 300

    // Layer 1: K = E
    gemm_gates_kernel<<<ggrid, gblk>>>(sent, W1, b1, E_DIM, 0);
    scan_kernel<<<sblocks, sthreads>>>(0, sent_len, out);

    // Layer 2: K = H
    gemm_gates_kernel<<<ggrid, gblk>>>(nullptr, W2, b2, H_DIM, 1);
    scan_kernel<<<sblocks, sthreads>>>(1, sent_len, out);

    // Layer 3: K = H, final pool fused into scan
    gemm_gates_kernel<<<ggrid, gblk>>>(nullptr, W3, b3, H_DIM, 1);
    scan_kernel<<<sblocks, sthreads>>>(2, sent_len, out);
}

// round 3
// speedup vs baseline: 2.3009x; 2.3009x over previous
#include <cuda_runtime.h>
#include <cuda_bf16.h>
#include <math.h>
#include <stdint.h>

// ---------------------------------------------------------------------------
// Problem constants
// ---------------------------------------------------------------------------
#define S_LEN 256
#define B_SZ  32
#define E_DIM 300
#define H_DIM 2400
#define N3H   (3 * H_DIM)            // 7200
#define M_ROWS (S_LEN * B_SZ)        // 8192

#define K1PAD 320                    // 300 -> mult of 32
#define K2PAD 2432                   // 2400 -> mult of 32
#define NPAD  7296                   // 7200 -> mult of 128

#define BM 128
#define BN 128
#define BK 32
#define NSTAGE 3

// SMEM: padded row stride 40 bf16 = 80 B (conflict-free ldmatrix, see theory)
#define ROWB 80
#define PLANE_BYTES (128 * ROWB)     // 10240
#define OFF_AHI 0
#define OFF_ALO (1 * PLANE_BYTES)
#define OFF_BHI (2 * PLANE_BYTES)
#define OFF_BLO (3 * PLANE_BYTES)
#define STAGE_BYTES (4 * PLANE_BYTES)            // 40960
#define GEMM_SMEM_BYTES (NSTAGE * STAGE_BYTES)   // 122880

// ---------------------------------------------------------------------------
// Scratch (__device__ globals: allocation-free; zero-initialized at load)
// ---------------------------------------------------------------------------
__device__ __align__(16) __nv_bfloat16 g_A1hi[(size_t)M_ROWS * K1PAD];
__device__ __align__(16) __nv_bfloat16 g_A1lo[(size_t)M_ROWS * K1PAD];
__device__ __align__(16) __nv_bfloat16 g_Axhi[(size_t)M_ROWS * K2PAD];
__device__ __align__(16) __nv_bfloat16 g_Axlo[(size_t)M_ROWS * K2PAD];
__device__ __align__(16) __nv_bfloat16 g_W1hi[(size_t)NPAD * K1PAD];
__device__ __align__(16) __nv_bfloat16 g_W1lo[(size_t)NPAD * K1PAD];
__device__ __align__(16) __nv_bfloat16 g_W2hi[(size_t)NPAD * K2PAD];
__device__ __align__(16) __nv_bfloat16 g_W2lo[(size_t)NPAD * K2PAD];
__device__ __align__(16) __nv_bfloat16 g_W3hi[(size_t)NPAD * K2PAD];
__device__ __align__(16) __nv_bfloat16 g_W3lo[(size_t)NPAD * K2PAD];
__device__ float g_gates[(size_t)M_ROWS * N3H];
__device__ float g_acc[B_SZ * H_DIM];

// ---------------------------------------------------------------------------
__device__ __forceinline__ uint32_t smem_u32(const void* p) {
    uint32_t a;
    asm("{ .reg .u64 t; cvta.to.shared.u64 t, %1; cvt.u32.u64 %0, t; }" : "=r"(a) : "l"(p));
    return a;
}
__device__ __forceinline__ float sigmoid_f(float x) {
    return __fdividef(1.0f, 1.0f + __expf(-x));
}

#define CP_ASYNC16(dst, src) \
    asm volatile("cp.async.cg.shared.global [%0], [%1], 16;" :: "r"(dst), "l"(src) : "memory")
#define CP_COMMIT() asm volatile("cp.async.commit_group;" ::: "memory")
#define CP_WAIT2()  asm volatile("cp.async.wait_group 2;" ::: "memory")

#define LDSM_X4(r0, r1, r2, r3, addr) \
    asm volatile("ldmatrix.sync.aligned.m8n8.x4.shared.b16 {%0,%1,%2,%3}, [%4];" \
                 : "=r"(r0), "=r"(r1), "=r"(r2), "=r"(r3) : "r"(addr))

#define MMA_BF16(d, a, b0, b1) \
    asm volatile("mma.sync.aligned.m16n8k16.row.col.f32.bf16.bf16.f32 " \
                 "{%0,%1,%2,%3}, {%4,%5,%6,%7}, {%8,%9}, {%0,%1,%2,%3};" \
                 : "+f"((d)[0]), "+f"((d)[1]), "+f"((d)[2]), "+f"((d)[3]) \
                 : "r"((a)[0]), "r"((a)[1]), "r"((a)[2]), "r"((a)[3]), "r"(b0), "r"(b1))

// ---------------------------------------------------------------------------
// fp32 -> split bf16 conversions
// ---------------------------------------------------------------------------
__global__ void cvt_W_kernel(const float* __restrict__ in, int K, int Kpad, int which) {
    __nv_bfloat16* hi = (which == 0) ? g_W1hi : (which == 1) ? g_W2hi : g_W3hi;
    __nv_bfloat16* lo = (which == 0) ? g_W1lo : (which == 1) ? g_W2lo : g_W3lo;
    const int r = blockIdx.y;
    const int k = blockIdx.x * 256 + threadIdx.x;
    if (k >= K) return;
    const float x = in[(size_t)r * K + k];
    const __nv_bfloat16 h = __float2bfloat16(x);
    hi[(size_t)r * Kpad + k] = h;
    lo[(size_t)r * Kpad + k] = __float2bfloat16(x - __bfloat162float(h));
}

__global__ void cvt_A1_kernel(const float* __restrict__ sent) {
    const int r = blockIdx.y;
    const int k = blockIdx.x * 256 + threadIdx.x;
    if (k >= E_DIM) return;
    const float x = sent[(size_t)r * E_DIM + k];
    const __nv_bfloat16 h = __float2bfloat16(x);
    g_A1hi[(size_t)r * K1PAD + k] = h;
    g_A1lo[(size_t)r * K1PAD + k] = __float2bfloat16(x - __bfloat162float(h));
}

// ---------------------------------------------------------------------------
// Split-bf16 HMMA GEMM: g_gates[m,n] = act( A[m,:] . W[n,:] + bias[n] )
// ---------------------------------------------------------------------------
__global__ __launch_bounds__(256) void gemm_tc(int layer, const float* __restrict__ bias) {
    const __nv_bfloat16 *Ahi, *Alo, *Whi, *Wlo;
    int Kpad;
    if (layer == 1)      { Ahi = g_A1hi; Alo = g_A1lo; Whi = g_W1hi; Wlo = g_W1lo; Kpad = K1PAD; }
    else if (layer == 2) { Ahi = g_Axhi; Alo = g_Axlo; Whi = g_W2hi; Wlo = g_W2lo; Kpad = K2PAD; }
    else                 { Ahi = g_Axhi; Alo = g_Axlo; Whi = g_W3hi; Wlo = g_W3lo; Kpad = K2PAD; }
    const int NT = Kpad / BK;

    // m-strip swizzle: strips of 8 m-groups; within a strip, n varies fastest
    // m-groups = 64, n-groups = 57.
    const int bx = blockIdx.x;
    const int strip = bx / (8 * 57);
    const int rem   = bx % (8 * 57);
    const int mg    = strip * 8 + (rem % 8);
    const int ng    = rem / 8;
    const int m0 = mg * BM;
    const int n0 = ng * BN;

    extern __shared__ char smem_raw[];
    const uint32_t sbase = smem_u32(smem_raw);

    const int tid = threadIdx.x;
    const int wid = tid >> 5;
    const int lid = tid & 31;
    const int wm = (wid & 1) * 64;     // warp m offset in tile
    const int wn = (wid >> 1) * 32;    // warp n offset in tile

    // --- async loader ---
    auto load_chunk = [&](int t, int slot) {
        const uint32_t st = sbase + (uint32_t)slot * STAGE_BYTES;
        const int kc = t * BK;
#pragma unroll
        for (int i = 0; i < 2; i++) {
            const int u = tid + i * 256;          // 0..511
            const int r = u >> 2, c = u & 3;      // row, 16B-unit
            const uint32_t so = (uint32_t)(r * ROWB + c * 16);
            const __nv_bfloat16* ah = Ahi + (size_t)(m0 + r) * Kpad + kc + c * 8;
            const __nv_bfloat16* al = Alo + (size_t)(m0 + r) * Kpad + kc + c * 8;
            const __nv_bfloat16* bh = Whi + (size_t)(n0 + r) * Kpad + kc + c * 8;
            const __nv_bfloat16* bl = Wlo + (size_t)(n0 + r) * Kpad + kc + c * 8;
            CP_ASYNC16(st + OFF_AHI + so, ah);
            CP_ASYNC16(st + OFF_ALO + so, al);
            CP_ASYNC16(st + OFF_BHI + so, bh);
            CP_ASYNC16(st + OFF_BLO + so, bl);
        }
        CP_COMMIT();
    };

    // Accumulators: d[mi][ni][4]
    float d[4][4][4];
#pragma unroll
    for (int mi = 0; mi < 4; mi++)
#pragma unroll
        for (int ni = 0; ni < 4; ni++)
#pragma unroll
            for (int q = 0; q < 4; q++) d[mi][ni][q] = 0.0f;

    // Lane-dependent smem offsets (within stage)
    // A: row = wm + mi*16 + (lid&15), koff(units of bf16) = (lid>>4)*8
    const uint32_t a_row = (uint32_t)(wm + (lid & 15));
    const uint32_t a_kb  = (uint32_t)((lid >> 4) * 16);          // bytes
    // B (x4 covers 2 n-tiles): n = wn + j*16 + (lid&7) + ((lid>>4)&1)*8
    //                          koff = ((lid>>3)&1)*8
    const uint32_t b_row = (uint32_t)(wn + (lid & 7) + ((lid >> 4) & 1) * 8);
    const uint32_t b_kb  = (uint32_t)(((lid >> 3) & 1) * 16);    // bytes

    // Prologue
    load_chunk(0, 0);
    load_chunk(1, 1);

    for (int t = 0; t < NT; ++t) {
        if (t + 2 < NT) load_chunk(t + 2, (t + 2) % NSTAGE);
        else CP_COMMIT();                       // keep group count uniform
        CP_WAIT2();
        __syncthreads();

        const uint32_t st = sbase + (uint32_t)(t % NSTAGE) * STAGE_BYTES;
#pragma unroll
        for (int ks = 0; ks < 2; ks++) {
            const uint32_t kbyte = (uint32_t)(ks * 32);
            uint32_t ahi[4][4], alo[4][4];
#pragma unroll
            for (int mi = 0; mi < 4; mi++) {
                const uint32_t ra = st + (a_row + mi * 16) * ROWB + kbyte + a_kb;
                LDSM_X4(ahi[mi][0], ahi[mi][1], ahi[mi][2], ahi[mi][3], ra + OFF_AHI);
                LDSM_X4(alo[mi][0], alo[mi][1], alo[mi][2], alo[mi][3], ra + OFF_ALO);
            }
            uint32_t bhi[4][2], blo[4][2];
#pragma unroll
            for (int j = 0; j < 2; j++) {
                const uint32_t rb = st + (b_row + j * 16) * ROWB + kbyte + b_kb;
                LDSM_X4(bhi[2*j][0], bhi[2*j][1], bhi[2*j+1][0], bhi[2*j+1][1], rb + OFF_BHI);
                LDSM_X4(blo[2*j][0], blo[2*j][1], blo[2*j+1][0], blo[2*j+1][1], rb + OFF_BLO);
            }
#pragma unroll
            for (int mi = 0; mi < 4; mi++)
#pragma unroll
                for (int ni = 0; ni < 4; ni++) {
                    MMA_BF16(d[mi][ni], ahi[mi], bhi[ni][0], bhi[ni][1]);
                    MMA_BF16(d[mi][ni], ahi[mi], blo[ni][0], blo[ni][1]);
                    MMA_BF16(d[mi][ni], alo[mi], bhi[ni][0], bhi[ni][1]);
                }
        }
        __syncthreads();
    }

    // Epilogue: bias + activation + store
    const int er = lid >> 2;            // 0..7
    const int ec = (lid & 3) * 2;       // 0,2,4,6
#pragma unroll
    for (int mi = 0; mi < 4; mi++) {
#pragma unroll
        for (int ni = 0; ni < 4; ni++) {
            const int n = n0 + wn + ni * 8 + ec;
            if (n >= N3H) continue;
            const int m = m0 + wm + mi * 16 + er;
            const float2 bs = *(const float2*)(bias + n);
            const bool is_tanh0 = (n < H_DIM);
            const bool is_tanh1 = (n + 1 < H_DIM);
            {
                float y0 = d[mi][ni][0] + bs.x;
                float y1 = d[mi][ni][1] + bs.y;
                float2 v;
                v.x = is_tanh0 ? tanhf(y0) : sigmoid_f(y0);
                v.y = is_tanh1 ? tanhf(y1) : sigmoid_f(y1);
                *(float2*)(g_gates + (size_t)m * N3H + n) = v;
            }
            {
                float y0 = d[mi][ni][2] + bs.x;
                float y1 = d[mi][ni][3] + bs.y;
                float2 v;
                v.x = is_tanh0 ? tanhf(y0) : sigmoid_f(y0);
                v.y = is_tanh1 ? tanhf(y1) : sigmoid_f(y1);
                *(float2*)(g_gates + (size_t)(m + 8) * N3H + n) = v;
            }
        }
    }
}

// ---------------------------------------------------------------------------
// fo-pool scan. mode 0: acc = c_last + write split x; 1: acc += c_last + write;
// 2: out = (acc + c_last)/sent_len
// ---------------------------------------------------------------------------
__global__ void scan_kernel(int mode, const int* __restrict__ sent_len,
                            float* __restrict__ out)
{
    const int idx = blockIdx.x * blockDim.x + threadIdx.x;
    if (idx >= B_SZ * H_DIM) return;
    const int b = idx / H_DIM;
    const int h = idx - b * H_DIM;

    const size_t stride = (size_t)B_SZ * N3H;
    size_t base = (size_t)b * N3H + h;

    float c = 0.0f;
    if (mode != 2) {
        size_t xbase = (size_t)b * K2PAD + h;
        const size_t xstride = (size_t)B_SZ * K2PAD;
#pragma unroll 4
        for (int s = 0; s < S_LEN; ++s) {
            const float z = g_gates[base];
            const float f = g_gates[base + H_DIM];
            const float o = g_gates[base + 2 * H_DIM];
            c = fmaf(f, c - z, z);
            const float hv = o * c;
            const __nv_bfloat16 hhi = __float2bfloat16(hv);
            g_Axhi[xbase] = hhi;
            g_Axlo[xbase] = __float2bfloat16(hv - __bfloat162float(hhi));
            base += stride;
            xbase += xstride;
        }
    } else {
#pragma unroll 4
        for (int s = 0; s < S_LEN; ++s) {
            const float z = g_gates[base];
            const float f = g_gates[base + H_DIM];
            c = fmaf(f, c - z, z);
            base += stride;
        }
    }

    if (mode == 0)      g_acc[idx] = c;
    else if (mode == 1) g_acc[idx] += c;
    else                out[idx] = (g_acc[idx] + c) / (float)sent_len[b];
}

// ---------------------------------------------------------------------------
extern "C" void kernel_launch(void* const* d_in, const int* in_sizes, int n_in,
                              void* d_out, int out_size)
{
    const float* sent     = (const float*)d_in[0];
    const int*   sent_len = (const int*)  d_in[1];
    const float* W1 = (const float*)d_in[2];
    const float* b1 = (const float*)d_in[3];
    const float* W2 = (const float*)d_in[4];
    const float* b2 = (const float*)d_in[5];
    const float* W3 = (const float*)d_in[6];
    const float* b3 = (const float*)d_in[7];
    float* out = (float*)d_out;

    cudaFuncSetAttribute(gemm_tc, cudaFuncAttributeMaxDynamicSharedMemorySize, GEMM_SMEM_BYTES);

    cvt_W_kernel<<<dim3(2,  N3H), 256>>>(W1, E_DIM, K1PAD, 0);
    cvt_W_kernel<<<dim3(10, N3H), 256>>>(W2, H_DIM, K2PAD, 1);
    cvt_W_kernel<<<dim3(10, N3H), 256>>>(W3, H_DIM, K2PAD, 2);
    cvt_A1_kernel<<<dim3(2, M_ROWS), 256>>>(sent);

    const int nblocks = (M_ROWS / BM) * (NPAD / BN);   // 64 * 57 = 3648
    const int sblocks = (B_SZ * H_DIM + 255) / 256;

    gemm_tc<<<nblocks, 256, GEMM_SMEM_BYTES>>>(1, b1);
    scan_kernel<<<sblocks, 256>>>(0, sent_len, out);

    gemm_tc<<<nblocks, 256, GEMM_SMEM_BYTES>>>(2, b2);
    scan_kernel<<<sblocks, 256>>>(1, sent_len, out);

    gemm_tc<<<nblocks, 256, GEMM_SMEM_BYTES>>>(3, b3);
    scan_kernel<<<sblocks, 256>>>(2, sent_len, out);
}

// round 4
// speedup vs baseline: 3.7693x; 1.6382x over previous
#include <cuda_runtime.h>
#include <cuda_fp16.h>
#include <math.h>
#include <stdint.h>

// ---------------------------------------------------------------------------
// Problem constants
// ---------------------------------------------------------------------------
#define S_LEN 256
#define B_SZ  32
#define E_DIM 300
#define H_DIM 2400
#define N3H   (3 * H_DIM)            // 7200
#define M_ROWS (S_LEN * B_SZ)        // 8192

#define K1PAD 320                    // 300 -> mult of 32
#define K2PAD 2432                   // 2400 -> mult of 32
#define NPAD  7296                   // 7200 -> mult of 128

#define BM 128
#define BN 128
#define BK 32
#define NSTAGE 3

// SMEM plane: 128 rows x BK fp16, padded row stride 80 B (conflict-free ldmatrix)
#define ROWB 80
#define PLANE_BYTES (128 * ROWB)     // 10240
#define OFF_A   0
#define OFF_BHI (1 * PLANE_BYTES)
#define OFF_BLO (2 * PLANE_BYTES)
#define STAGE_BYTES (3 * PLANE_BYTES)            // 30720
#define GEMM_SMEM_BYTES (NSTAGE * STAGE_BYTES)   // 92160

// ---------------------------------------------------------------------------
// Scratch (__device__ globals: allocation-free; zero-initialized at load,
// so padded K/N regions read as 0)
// ---------------------------------------------------------------------------
__device__ __align__(16) __half g_A1[(size_t)M_ROWS * K1PAD];
__device__ __align__(16) __half g_Ax[(size_t)M_ROWS * K2PAD];
__device__ __align__(16) __half g_W1hi[(size_t)NPAD * K1PAD];
__device__ __align__(16) __half g_W1lo[(size_t)NPAD * K1PAD];
__device__ __align__(16) __half g_W2hi[(size_t)NPAD * K2PAD];
__device__ __align__(16) __half g_W2lo[(size_t)NPAD * K2PAD];
__device__ __align__(16) __half g_W3hi[(size_t)NPAD * K2PAD];
__device__ __align__(16) __half g_W3lo[(size_t)NPAD * K2PAD];
__device__ float g_gates[(size_t)M_ROWS * N3H];
__device__ float g_acc[B_SZ * H_DIM];

// ---------------------------------------------------------------------------
__device__ __forceinline__ uint32_t smem_u32(const void* p) {
    uint32_t a;
    asm("{ .reg .u64 t; cvta.to.shared.u64 t, %1; cvt.u32.u64 %0, t; }" : "=r"(a) : "l"(p));
    return a;
}
__device__ __forceinline__ float sigmoid_f(float x) {
    return __fdividef(1.0f, 1.0f + __expf(-x));
}
__device__ __forceinline__ float tanh_fast(float x) {
    // exact at +-inf; ~1e-6 abs error via MUFU ex2
    return 1.0f - __fdividef(2.0f, __expf(2.0f * x) + 1.0f);
}

#define CP_ASYNC16(dst, src) \
    asm volatile("cp.async.cg.shared.global [%0], [%1], 16;" :: "r"(dst), "l"(src) : "memory")
#define CP_COMMIT() asm volatile("cp.async.commit_group;" ::: "memory")
#define CP_WAIT2()  asm volatile("cp.async.wait_group 2;" ::: "memory")

#define LDSM_X4(r0, r1, r2, r3, addr) \
    asm volatile("ldmatrix.sync.aligned.m8n8.x4.shared.b16 {%0,%1,%2,%3}, [%4];" \
                 : "=r"(r0), "=r"(r1), "=r"(r2), "=r"(r3) : "r"(addr))

#define MMA_FP16(d, a, b0, b1) \
    asm volatile("mma.sync.aligned.m16n8k16.row.col.f32.f16.f16.f32 " \
                 "{%0,%1,%2,%3}, {%4,%5,%6,%7}, {%8,%9}, {%0,%1,%2,%3};" \
                 : "+f"((d)[0]), "+f"((d)[1]), "+f"((d)[2]), "+f"((d)[3]) \
                 : "r"((a)[0]), "r"((a)[1]), "r"((a)[2]), "r"((a)[3]), "r"(b0), "r"(b1))

// ---------------------------------------------------------------------------
// fp32 -> fp16 conversions (weights: hi + residual lo; activations: hi only)
// ---------------------------------------------------------------------------
__global__ void cvt_W_kernel(const float* __restrict__ in, int K, int Kpad, int which) {
    __half* hi = (which == 0) ? g_W1hi : (which == 1) ? g_W2hi : g_W3hi;
    __half* lo = (which == 0) ? g_W1lo : (which == 1) ? g_W2lo : g_W3lo;
    const int r = blockIdx.y;
    const int k = blockIdx.x * 256 + threadIdx.x;
    if (k >= K) return;
    const float x = in[(size_t)r * K + k];
    const __half h = __float2half_rn(x);
    hi[(size_t)r * Kpad + k] = h;
    lo[(size_t)r * Kpad + k] = __float2half_rn(x - __half2float(h));
}

__global__ void cvt_A1_kernel(const float* __restrict__ sent) {
    const int r = blockIdx.y;
    const int k = blockIdx.x * 256 + threadIdx.x;
    if (k >= E_DIM) return;
    g_A1[(size_t)r * K1PAD + k] = __float2half_rn(sent[(size_t)r * E_DIM + k]);
}

// ---------------------------------------------------------------------------
// 2-term split-fp16 HMMA GEMM: g_gates[m,n] = act( A[m,:].W[n,:] + bias[n] )
// D = A * Whi + A * Wlo  (fp32 accumulate)
// ---------------------------------------------------------------------------
__global__ __launch_bounds__(256) void gemm_tc(int layer, const float* __restrict__ bias) {
    const __half *A, *Whi, *Wlo;
    int Kpad;
    if (layer == 1)      { A = g_A1; Whi = g_W1hi; Wlo = g_W1lo; Kpad = K1PAD; }
    else if (layer == 2) { A = g_Ax; Whi = g_W2hi; Wlo = g_W2lo; Kpad = K2PAD; }
    else                 { A = g_Ax; Whi = g_W3hi; Wlo = g_W3lo; Kpad = K2PAD; }
    const int NT = Kpad / BK;

    // m-strip swizzle for L2 reuse: strips of 8 m-groups, n fastest
    const int bx = blockIdx.x;
    const int strip = bx / (8 * 57);
    const int rem   = bx % (8 * 57);
    const int mg    = strip * 8 + (rem % 8);
    const int ng    = rem / 8;
    const int m0 = mg * BM;
    const int n0 = ng * BN;

    extern __shared__ char smem_raw[];
    const uint32_t sbase = smem_u32(smem_raw);

    const int tid = threadIdx.x;
    const int wid = tid >> 5;
    const int lid = tid & 31;
    const int wm = (wid & 1) * 64;
    const int wn = (wid >> 1) * 32;

    auto load_chunk = [&](int t, int slot) {
        const uint32_t st = sbase + (uint32_t)slot * STAGE_BYTES;
        const int kc = t * BK;
#pragma unroll
        for (int i = 0; i < 2; i++) {
            const int u = tid + i * 256;          // 0..511
            const int r = u >> 2, c = u & 3;      // row, 16B-unit (4 units/row of 64B)
            const uint32_t so = (uint32_t)(r * ROWB + c * 16);
            CP_ASYNC16(st + OFF_A   + so, A   + (size_t)(m0 + r) * Kpad + kc + c * 8);
            CP_ASYNC16(st + OFF_BHI + so, Whi + (size_t)(n0 + r) * Kpad + kc + c * 8);
            CP_ASYNC16(st + OFF_BLO + so, Wlo + (size_t)(n0 + r) * Kpad + kc + c * 8);
        }
        CP_COMMIT();
    };

    float d[4][4][4];
#pragma unroll
    for (int mi = 0; mi < 4; mi++)
#pragma unroll
        for (int ni = 0; ni < 4; ni++)
#pragma unroll
            for (int q = 0; q < 4; q++) d[mi][ni][q] = 0.0f;

    // ldmatrix lane addressing
    const uint32_t a_row = (uint32_t)(wm + (lid & 15));
    const uint32_t a_kb  = (uint32_t)((lid >> 4) * 16);
    const uint32_t b_row = (uint32_t)(wn + (lid & 7) + ((lid >> 4) & 1) * 8);
    const uint32_t b_kb  = (uint32_t)(((lid >> 3) & 1) * 16);

    load_chunk(0, 0);
    load_chunk(1, 1);

    for (int t = 0; t < NT; ++t) {
        if (t + 2 < NT) load_chunk(t + 2, (t + 2) % NSTAGE);
        else CP_COMMIT();
        CP_WAIT2();
        __syncthreads();

        const uint32_t st = sbase + (uint32_t)(t % NSTAGE) * STAGE_BYTES;
#pragma unroll
        for (int ks = 0; ks < 2; ks++) {
            const uint32_t kbyte = (uint32_t)(ks * 32);
            uint32_t af[4][4];
#pragma unroll
            for (int mi = 0; mi < 4; mi++) {
                const uint32_t ra = st + (a_row + mi * 16) * ROWB + kbyte + a_kb;
                LDSM_X4(af[mi][0], af[mi][1], af[mi][2], af[mi][3], ra + OFF_A);
            }
            uint32_t bhi[4][2], blo[4][2];
#pragma unroll
            for (int j = 0; j < 2; j++) {
                const uint32_t rb = st + (b_row + j * 16) * ROWB + kbyte + b_kb;
                LDSM_X4(bhi[2*j][0], bhi[2*j][1], bhi[2*j+1][0], bhi[2*j+1][1], rb + OFF_BHI);
                LDSM_X4(blo[2*j][0], blo[2*j][1], blo[2*j+1][0], blo[2*j+1][1], rb + OFF_BLO);
            }
#pragma unroll
            for (int mi = 0; mi < 4; mi++)
#pragma unroll
                for (int ni = 0; ni < 4; ni++) {
                    MMA_FP16(d[mi][ni], af[mi], bhi[ni][0], bhi[ni][1]);
                    MMA_FP16(d[mi][ni], af[mi], blo[ni][0], blo[ni][1]);
                }
        }
        __syncthreads();
    }

    // Epilogue: bias + activation + store fp32 gates
    const int er = lid >> 2;
    const int ec = (lid & 3) * 2;
#pragma unroll
    for (int mi = 0; mi < 4; mi++) {
#pragma unroll
        for (int ni = 0; ni < 4; ni++) {
            const int n = n0 + wn + ni * 8 + ec;
            if (n >= N3H) continue;
            const int m = m0 + wm + mi * 16 + er;
            const float2 bs = *(const float2*)(bias + n);
            const bool t0 = (n < H_DIM);
            const bool t1 = (n + 1 < H_DIM);
            {
                float y0 = d[mi][ni][0] + bs.x;
                float y1 = d[mi][ni][1] + bs.y;
                float2 v;
                v.x = t0 ? tanh_fast(y0) : sigmoid_f(y0);
                v.y = t1 ? tanh_fast(y1) : sigmoid_f(y1);
                *(float2*)(g_gates + (size_t)m * N3H + n) = v;
            }
            {
                float y0 = d[mi][ni][2] + bs.x;
                float y1 = d[mi][ni][3] + bs.y;
                float2 v;
                v.x = t0 ? tanh_fast(y0) : sigmoid_f(y0);
                v.y = t1 ? tanh_fast(y1) : sigmoid_f(y1);
                *(float2*)(g_gates + (size_t)(m + 8) * N3H + n) = v;
            }
        }
    }
}

// ---------------------------------------------------------------------------
// fo-pool scan: 4 h-lanes per thread (float4 streams, 4 independent chains).
// mode 0: acc = c_last + write x; 1: acc += c_last + write x;
// 2: out = (acc + c_last)/sent_len (no x writes)
// ---------------------------------------------------------------------------
__global__ void scan_kernel(int mode, const int* __restrict__ sent_len,
                            float* __restrict__ out)
{
    const int tix = blockIdx.x * blockDim.x + threadIdx.x;   // 0..19199
    if (tix >= (B_SZ * H_DIM) / 4) return;
    const int flat = tix * 4;
    const int b = flat / H_DIM;
    const int h = flat - b * H_DIM;       // mult of 4 (H_DIM % 4 == 0)

    const size_t stride = (size_t)B_SZ * N3H;
    size_t base = (size_t)b * N3H + h;

    float4 c = make_float4(0.f, 0.f, 0.f, 0.f);

    if (mode != 2) {
        size_t xbase = (size_t)b * K2PAD + h;
        const size_t xstride = (size_t)B_SZ * K2PAD;
#pragma unroll 4
        for (int s = 0; s < S_LEN; ++s) {
            const float4 z = *(const float4*)(g_gates + base);
            const float4 f = *(const float4*)(g_gates + base + H_DIM);
            const float4 o = *(const float4*)(g_gates + base + 2 * H_DIM);
            c.x = fmaf(f.x, c.x - z.x, z.x);
            c.y = fmaf(f.y, c.y - z.y, z.y);
            c.z = fmaf(f.z, c.z - z.z, z.z);
            c.w = fmaf(f.w, c.w - z.w, z.w);
            __half2 h01 = __floats2half2_rn(o.x * c.x, o.y * c.y);
            __half2 h23 = __floats2half2_rn(o.z * c.z, o.w * c.w);
            uint2 pk;
            pk.x = *(uint32_t*)&h01;
            pk.y = *(uint32_t*)&h23;
            *(uint2*)(g_Ax + xbase) = pk;
            base  += stride;
            xbase += xstride;
        }
    } else {
#pragma unroll 4
        for (int s = 0; s < S_LEN; ++s) {
            const float4 z = *(const float4*)(g_gates + base);
            const float4 f = *(const float4*)(g_gates + base + H_DIM);
            c.x = fmaf(f.x, c.x - z.x, z.x);
            c.y = fmaf(f.y, c.y - z.y, z.y);
            c.z = fmaf(f.z, c.z - z.z, z.z);
            c.w = fmaf(f.w, c.w - z.w, z.w);
            base += stride;
        }
    }

    if (mode == 0) {
        *(float4*)(g_acc + flat) = c;
    } else if (mode == 1) {
        float4 a = *(const float4*)(g_acc + flat);
        a.x += c.x; a.y += c.y; a.z += c.z; a.w += c.w;
        *(float4*)(g_acc + flat) = a;
    } else {
        const float inv = 1.0f / (float)sent_len[b];
        float4 a = *(const float4*)(g_acc + flat);
        float4 v;
        v.x = (a.x + c.x) * inv;
        v.y = (a.y + c.y) * inv;
        v.z = (a.z + c.z) * inv;
        v.w = (a.w + c.w) * inv;
        *(float4*)(out + flat) = v;
    }
}

// ---------------------------------------------------------------------------
extern "C" void kernel_launch(void* const* d_in, const int* in_sizes, int n_in,
                              void* d_out, int out_size)
{
    const float* sent     = (const float*)d_in[0];
    const int*   sent_len = (const int*)  d_in[1];
    const float* W1 = (const float*)d_in[2];
    const float* b1 = (const float*)d_in[3];
    const float* W2 = (const float*)d_in[4];
    const float* b2 = (const float*)d_in[5];
    const float* W3 = (const float*)d_in[6];
    const float* b3 = (const float*)d_in[7];
    float* out = (float*)d_out;

    cudaFuncSetAttribute(gemm_tc, cudaFuncAttributeMaxDynamicSharedMemorySize, GEMM_SMEM_BYTES);

    cvt_W_kernel<<<dim3(2,  N3H), 256>>>(W1, E_DIM, K1PAD, 0);
    cvt_W_kernel<<<dim3(10, N3H), 256>>>(W2, H_DIM, K2PAD, 1);
    cvt_W_kernel<<<dim3(10, N3H), 256>>>(W3, H_DIM, K2PAD, 2);
    cvt_A1_kernel<<<dim3(2, M_ROWS), 256>>>(sent);

    const int nblocks = (M_ROWS / BM) * (NPAD / BN);      // 64 * 57 = 3648
    const int sblocks = ((B_SZ * H_DIM) / 4 + 127) / 128; // 150

    gemm_tc<<<nblocks, 256, GEMM_SMEM_BYTES>>>(1, b1);
    scan_kernel<<<sblocks, 128>>>(0, sent_len, out);

    gemm_tc<<<nblocks, 256, GEMM_SMEM_BYTES>>>(2, b2);
    scan_kernel<<<sblocks, 128>>>(1, sent_len, out);

    gemm_tc<<<nblocks, 256, GEMM_SMEM_BYTES>>>(3, b3);
    scan_kernel<<<sblocks, 128>>>(2, sent_len, out);
}

// round 5
// speedup vs baseline: 3.9059x; 1.0362x over previous
#include <cuda_runtime.h>
#include <cuda_fp16.h>
#include <math.h>
#include <stdint.h>

// ---------------------------------------------------------------------------
// Problem constants
// ---------------------------------------------------------------------------
#define S_LEN 256
#define B_SZ  32
#define E_DIM 300
#define H_DIM 2400
#define N3H   (3 * H_DIM)            // 7200
#define M_ROWS (S_LEN * B_SZ)        // 8192

#define K1PAD 320                    // 300 -> mult of 32
#define K2PAD 2432                   // 2400 -> mult of 32
#define NPAD  7296                   // 7200 -> mult of 128

#define BM 128
#define BN 128
#define BK 32
#define NSTAGE 3

// SMEM plane: 128 rows x BK fp16, padded row stride 80 B (conflict-free ldmatrix)
#define ROWB 80
#define PLANE_BYTES (128 * ROWB)     // 10240
#define OFF_A   0
#define OFF_BHI (1 * PLANE_BYTES)
#define OFF_BLO (2 * PLANE_BYTES)
#define STAGE_BYTES (3 * PLANE_BYTES)            // 30720
#define GEMM_SMEM_BYTES (NSTAGE * STAGE_BYTES)   // 92160 (x2 CTA = 184320 <= 228K)

// ---------------------------------------------------------------------------
// Scratch (__device__ globals: allocation-free; zero-initialized at load,
// so padded K/N regions read as 0)
// ---------------------------------------------------------------------------
__device__ __align__(16) __half g_A1[(size_t)M_ROWS * K1PAD];
__device__ __align__(16) __half g_Ax[(size_t)M_ROWS * K2PAD];
__device__ __align__(16) __half g_W1hi[(size_t)NPAD * K1PAD];
__device__ __align__(16) __half g_W1lo[(size_t)NPAD * K1PAD];
__device__ __align__(16) __half g_W2hi[(size_t)NPAD * K2PAD];
__device__ __align__(16) __half g_W2lo[(size_t)NPAD * K2PAD];
__device__ __align__(16) __half g_W3hi[(size_t)NPAD * K2PAD];
__device__ __align__(16) __half g_W3lo[(size_t)NPAD * K2PAD];
__device__ __align__(16) __half g_gates[(size_t)M_ROWS * N3H];   // fp16 gates
__device__ float g_acc[B_SZ * H_DIM];

// ---------------------------------------------------------------------------
__device__ __forceinline__ uint32_t smem_u32(const void* p) {
    uint32_t a;
    asm("{ .reg .u64 t; cvta.to.shared.u64 t, %1; cvt.u32.u64 %0, t; }" : "=r"(a) : "l"(p));
    return a;
}
__device__ __forceinline__ float sigmoid_f(float x) {
    return __fdividef(1.0f, 1.0f + __expf(-x));
}
__device__ __forceinline__ float tanh_fast(float x) {
    return 1.0f - __fdividef(2.0f, __expf(2.0f * x) + 1.0f);
}

#define CP_ASYNC16(dst, src) \
    asm volatile("cp.async.cg.shared.global [%0], [%1], 16;" :: "r"(dst), "l"(src) : "memory")
#define CP_COMMIT() asm volatile("cp.async.commit_group;" ::: "memory")
#define CP_WAIT2()  asm volatile("cp.async.wait_group 2;" ::: "memory")

#define LDSM_X4(r0, r1, r2, r3, addr) \
    asm volatile("ldmatrix.sync.aligned.m8n8.x4.shared.b16 {%0,%1,%2,%3}, [%4];" \
                 : "=r"(r0), "=r"(r1), "=r"(r2), "=r"(r3) : "r"(addr))

#define MMA_FP16(d, a, b0, b1) \
    asm volatile("mma.sync.aligned.m16n8k16.row.col.f32.f16.f16.f32 " \
                 "{%0,%1,%2,%3}, {%4,%5,%6,%7}, {%8,%9}, {%0,%1,%2,%3};" \
                 : "+f"((d)[0]), "+f"((d)[1]), "+f"((d)[2]), "+f"((d)[3]) \
                 : "r"((a)[0]), "r"((a)[1]), "r"((a)[2]), "r"((a)[3]), "r"(b0), "r"(b1))

// ---------------------------------------------------------------------------
// fp32 -> fp16 conversions, vectorized (float4 in, uint2-of-half out)
// ---------------------------------------------------------------------------
__global__ void cvt_W_kernel(const float* __restrict__ in, int K4, int Kpad, int which) {
    __half* hi = (which == 0) ? g_W1hi : (which == 1) ? g_W2hi : g_W3hi;
    __half* lo = (which == 0) ? g_W1lo : (which == 1) ? g_W2lo : g_W3lo;
    const int r = blockIdx.x;
    const float4* row = (const float4*)(in + (size_t)r * (K4 * 4));
    for (int k4 = threadIdx.x; k4 < K4; k4 += blockDim.x) {
        const float4 x = row[k4];
        __half2 h01 = __floats2half2_rn(x.x, x.y);
        __half2 h23 = __floats2half2_rn(x.z, x.w);
        const float2 f01 = __half22float2(h01);
        const float2 f23 = __half22float2(h23);
        __half2 l01 = __floats2half2_rn(x.x - f01.x, x.y - f01.y);
        __half2 l23 = __floats2half2_rn(x.z - f23.x, x.w - f23.y);
        const size_t o = (size_t)r * Kpad + k4 * 4;
        uint2 ph, pl;
        ph.x = *(uint32_t*)&h01; ph.y = *(uint32_t*)&h23;
        pl.x = *(uint32_t*)&l01; pl.y = *(uint32_t*)&l23;
        *(uint2*)(hi + o) = ph;
        *(uint2*)(lo + o) = pl;
    }
}

__global__ void cvt_A1_kernel(const float* __restrict__ sent) {
    const int r = blockIdx.x;
    const float4* row = (const float4*)(sent + (size_t)r * E_DIM);
    for (int k4 = threadIdx.x; k4 < E_DIM / 4; k4 += blockDim.x) {
        const float4 x = row[k4];
        __half2 h01 = __floats2half2_rn(x.x, x.y);
        __half2 h23 = __floats2half2_rn(x.z, x.w);
        uint2 ph;
        ph.x = *(uint32_t*)&h01; ph.y = *(uint32_t*)&h23;
        *(uint2*)(g_A1 + (size_t)r * K1PAD + k4 * 4) = ph;
    }
}

// ---------------------------------------------------------------------------
// 2-term split-fp16 HMMA GEMM: g_gates[m,n] = act( A[m,:].W[n,:] + bias[n] )
// D = A * Whi + A * Wlo (fp32 accumulate). 2 CTAs/SM.
// ---------------------------------------------------------------------------
__global__ __launch_bounds__(256, 2) void gemm_tc(int layer, const float* __restrict__ bias) {
    const __half *A, *Whi, *Wlo;
    int Kpad;
    if (layer == 1)      { A = g_A1; Whi = g_W1hi; Wlo = g_W1lo; Kpad = K1PAD; }
    else if (layer == 2) { A = g_Ax; Whi = g_W2hi; Wlo = g_W2lo; Kpad = K2PAD; }
    else                 { A = g_Ax; Whi = g_W3hi; Wlo = g_W3lo; Kpad = K2PAD; }
    const int NT = Kpad / BK;

    // m-strip swizzle for L2 reuse: strips of 8 m-groups, n fastest
    const int bx = blockIdx.x;
    const int strip = bx / (8 * 57);
    const int rem   = bx % (8 * 57);
    const int mg    = strip * 8 + (rem % 8);
    const int ng    = rem / 8;
    const int m0 = mg * BM;
    const int n0 = ng * BN;

    extern __shared__ char smem_raw[];
    const uint32_t sbase = smem_u32(smem_raw);

    const int tid = threadIdx.x;
    const int wid = tid >> 5;
    const int lid = tid & 31;
    const int wm = (wid & 1) * 64;
    const int wn = (wid >> 1) * 32;

    auto load_chunk = [&](int t, int slot) {
        const uint32_t st = sbase + (uint32_t)slot * STAGE_BYTES;
        const int kc = t * BK;
#pragma unroll
        for (int i = 0; i < 2; i++) {
            const int u = tid + i * 256;          // 0..511
            const int r = u >> 2, c = u & 3;
            const uint32_t so = (uint32_t)(r * ROWB + c * 16);
            CP_ASYNC16(st + OFF_A   + so, A   + (size_t)(m0 + r) * Kpad + kc + c * 8);
            CP_ASYNC16(st + OFF_BHI + so, Whi + (size_t)(n0 + r) * Kpad + kc + c * 8);
            CP_ASYNC16(st + OFF_BLO + so, Wlo + (size_t)(n0 + r) * Kpad + kc + c * 8);
        }
        CP_COMMIT();
    };

    float d[4][4][4];
#pragma unroll
    for (int mi = 0; mi < 4; mi++)
#pragma unroll
        for (int ni = 0; ni < 4; ni++)
#pragma unroll
            for (int q = 0; q < 4; q++) d[mi][ni][q] = 0.0f;

    const uint32_t a_row = (uint32_t)(wm + (lid & 15));
    const uint32_t a_kb  = (uint32_t)((lid >> 4) * 16);
    const uint32_t b_row = (uint32_t)(wn + (lid & 7) + ((lid >> 4) & 1) * 8);
    const uint32_t b_kb  = (uint32_t)(((lid >> 3) & 1) * 16);

    load_chunk(0, 0);
    load_chunk(1, 1);

    for (int t = 0; t < NT; ++t) {
        if (t + 2 < NT) load_chunk(t + 2, (t + 2) % NSTAGE);
        else CP_COMMIT();
        CP_WAIT2();
        __syncthreads();

        const uint32_t st = sbase + (uint32_t)(t % NSTAGE) * STAGE_BYTES;
#pragma unroll
        for (int ks = 0; ks < 2; ks++) {
            const uint32_t kbyte = (uint32_t)(ks * 32);
            uint32_t af[4][4];
#pragma unroll
            for (int mi = 0; mi < 4; mi++) {
                const uint32_t ra = st + (a_row + mi * 16) * ROWB + kbyte + a_kb;
                LDSM_X4(af[mi][0], af[mi][1], af[mi][2], af[mi][3], ra + OFF_A);
            }
            uint32_t bhi[4][2], blo[4][2];
#pragma unroll
            for (int j = 0; j < 2; j++) {
                const uint32_t rb = st + (b_row + j * 16) * ROWB + kbyte + b_kb;
                LDSM_X4(bhi[2*j][0], bhi[2*j][1], bhi[2*j+1][0], bhi[2*j+1][1], rb + OFF_BHI);
                LDSM_X4(blo[2*j][0], blo[2*j][1], blo[2*j+1][0], blo[2*j+1][1], rb + OFF_BLO);
            }
#pragma unroll
            for (int mi = 0; mi < 4; mi++)
#pragma unroll
                for (int ni = 0; ni < 4; ni++) {
                    MMA_FP16(d[mi][ni], af[mi], bhi[ni][0], bhi[ni][1]);
                    MMA_FP16(d[mi][ni], af[mi], blo[ni][0], blo[ni][1]);
                }
        }
        __syncthreads();
    }

    // Epilogue: bias + activation + fp16 store
    const int er = lid >> 2;
    const int ec = (lid & 3) * 2;
#pragma unroll
    for (int mi = 0; mi < 4; mi++) {
#pragma unroll
        for (int ni = 0; ni < 4; ni++) {
            const int n = n0 + wn + ni * 8 + ec;     // even; H_DIM even -> no straddle
            if (n >= N3H) continue;
            const int m = m0 + wm + mi * 16 + er;
            const float2 bs = *(const float2*)(bias + n);
            const bool tA = (n < H_DIM);
            {
                const float y0 = d[mi][ni][0] + bs.x;
                const float y1 = d[mi][ni][1] + bs.y;
                const float v0 = tA ? tanh_fast(y0) : sigmoid_f(y0);
                const float v1 = tA ? tanh_fast(y1) : sigmoid_f(y1);
                *(__half2*)(g_gates + (size_t)m * N3H + n) = __floats2half2_rn(v0, v1);
            }
            {
                const float y0 = d[mi][ni][2] + bs.x;
                const float y1 = d[mi][ni][3] + bs.y;
                const float v0 = tA ? tanh_fast(y0) : sigmoid_f(y0);
                const float v1 = tA ? tanh_fast(y1) : sigmoid_f(y1);
                *(__half2*)(g_gates + (size_t)(m + 8) * N3H + n) = __floats2half2_rn(v0, v1);
            }
        }
    }
}

// ---------------------------------------------------------------------------
// fo-pool scan: 4 h-lanes/thread, fp16 gate reads (uint2), fp32 recurrence.
// mode 0: acc = c_last + write x; 1: acc += c_last + write x;
// 2: out = (acc + c_last)/sent_len
// ---------------------------------------------------------------------------
__device__ __forceinline__ float4 ld_gates4(const __half* p) {
    const uint2 u = *(const uint2*)p;
    const float2 a = __half22float2(*(const __half2*)&u.x);
    const float2 b = __half22float2(*(const __half2*)&u.y);
    return make_float4(a.x, a.y, b.x, b.y);
}

__global__ void scan_kernel(int mode, const int* __restrict__ sent_len,
                            float* __restrict__ out)
{
    const int tix = blockIdx.x * blockDim.x + threadIdx.x;
    if (tix >= (B_SZ * H_DIM) / 4) return;
    const int flat = tix * 4;
    const int b = flat / H_DIM;
    const int h = flat - b * H_DIM;

    const size_t stride = (size_t)B_SZ * N3H;
    size_t base = (size_t)b * N3H + h;

    float4 c = make_float4(0.f, 0.f, 0.f, 0.f);

    if (mode != 2) {
        size_t xbase = (size_t)b * K2PAD + h;
        const size_t xstride = (size_t)B_SZ * K2PAD;
#pragma unroll 4
        for (int s = 0; s < S_LEN; ++s) {
            const float4 z = ld_gates4(g_gates + base);
            const float4 f = ld_gates4(g_gates + base + H_DIM);
            const float4 o = ld_gates4(g_gates + base + 2 * H_DIM);
            c.x = fmaf(f.x, c.x - z.x, z.x);
            c.y = fmaf(f.y, c.y - z.y, z.y);
            c.z = fmaf(f.z, c.z - z.z, z.z);
            c.w = fmaf(f.w, c.w - z.w, z.w);
            __half2 h01 = __floats2half2_rn(o.x * c.x, o.y * c.y);
            __half2 h23 = __floats2half2_rn(o.z * c.z, o.w * c.w);
            uint2 pk;
            pk.x = *(uint32_t*)&h01;
            pk.y = *(uint32_t*)&h23;
            *(uint2*)(g_Ax + xbase) = pk;
            base  += stride;
            xbase += xstride;
        }
    } else {
#pragma unroll 4
        for (int s = 0; s < S_LEN; ++s) {
            const float4 z = ld_gates4(g_gates + base);
            const float4 f = ld_gates4(g_gates + base + H_DIM);
            c.x = fmaf(f.x, c.x - z.x, z.x);
            c.y = fmaf(f.y, c.y - z.y, z.y);
            c.z = fmaf(f.z, c.z - z.z, z.z);
            c.w = fmaf(f.w, c.w - z.w, z.w);
            base += stride;
        }
    }

    if (mode == 0) {
        *(float4*)(g_acc + flat) = c;
    } else if (mode == 1) {
        float4 a = *(const float4*)(g_acc + flat);
        a.x += c.x; a.y += c.y; a.z += c.z; a.w += c.w;
        *(float4*)(g_acc + flat) = a;
    } else {
        const float inv = 1.0f / (float)sent_len[b];
        float4 a = *(const float4*)(g_acc + flat);
        float4 v;
        v.x = (a.x + c.x) * inv;
        v.y = (a.y + c.y) * inv;
        v.z = (a.z + c.z) * inv;
        v.w = (a.w + c.w) * inv;
        *(float4*)(out + flat) = v;
    }
}

// ---------------------------------------------------------------------------
extern "C" void kernel_launch(void* const* d_in, const int* in_sizes, int n_in,
                              void* d_out, int out_size)
{
    const float* sent     = (const float*)d_in[0];
    const int*   sent_len = (const int*)  d_in[1];
    const float* W1 = (const float*)d_in[2];
    const float* b1 = (const float*)d_in[3];
    const float* W2 = (const float*)d_in[4];
    const float* b2 = (const float*)d_in[5];
    const float* W3 = (const float*)d_in[6];
    const float* b3 = (const float*)d_in[7];
    float* out = (float*)d_out;

    cudaFuncSetAttribute(gemm_tc, cudaFuncAttributeMaxDynamicSharedMemorySize, GEMM_SMEM_BYTES);

    cvt_W_kernel<<<N3H, 128>>>(W1, E_DIM / 4, K1PAD, 0);
    cvt_W_kernel<<<N3H, 128>>>(W2, H_DIM / 4, K2PAD, 1);
    cvt_W_kernel<<<N3H, 128>>>(W3, H_DIM / 4, K2PAD, 2);
    cvt_A1_kernel<<<M_ROWS, 64>>>(sent);

    const int nblocks = (M_ROWS / BM) * (NPAD / BN);      // 64 * 57 = 3648
    const int sblocks = ((B_SZ * H_DIM) / 4 + 127) / 128; // 150

    gemm_tc<<<nblocks, 256, GEMM_SMEM_BYTES>>>(1, b1);
    scan_kernel<<<sblocks, 128>>>(0, sent_len, out);

    gemm_tc<<<nblocks, 256, GEMM_SMEM_BYTES>>>(2, b2);
    scan_kernel<<<sblocks, 128>>>(1, sent_len, out);

    gemm_tc<<<nblocks, 256, GEMM_SMEM_BYTES>>>(3, b3);
    scan_kernel<<<sblocks, 128>>>(2, sent_len, out);
}

// round 6
// speedup vs baseline: 6.2576x; 1.6021x over previous
#include <cuda_runtime.h>
#include <cuda_fp16.h>
#include <math.h>
#include <stdint.h>

// ---------------------------------------------------------------------------
// Problem constants
// ---------------------------------------------------------------------------
#define S_LEN 256
#define B_SZ  32
#define E_DIM 300
#define H_DIM 2400
#define N3H   (3 * H_DIM)            // 7200
#define M_ROWS (S_LEN * B_SZ)        // 8192

#define K1PAD 320                    // 300 -> mult of 32
#define K2PAD 2432                   // 2400 -> mult of 32
#define NPAD  7296                   // 7200 -> mult of 128

#define BM 128
#define BN 128
#define BK 32
#define NSTAGE 4

// SMEM plane: 128 rows x BK fp16, padded row stride 80 B (conflict-free ldmatrix)
#define ROWB 80
#define PLANE_BYTES (128 * ROWB)     // 10240
#define OFF_A   0
#define OFF_B   (1 * PLANE_BYTES)
#define STAGE_BYTES (2 * PLANE_BYTES)            // 20480
#define GEMM_SMEM_BYTES (NSTAGE * STAGE_BYTES)   // 81920 (x2 CTA = 163840 <= 228K)

// ---------------------------------------------------------------------------
// Scratch (__device__ globals: allocation-free; zero-initialized at load,
// so padded K/N regions read as 0)
// ---------------------------------------------------------------------------
__device__ __align__(16) __half g_A1[(size_t)M_ROWS * K1PAD];
__device__ __align__(16) __half g_Ax[(size_t)M_ROWS * K2PAD];
__device__ __align__(16) __half g_W1[(size_t)NPAD * K1PAD];
__device__ __align__(16) __half g_W2[(size_t)NPAD * K2PAD];
__device__ __align__(16) __half g_W3[(size_t)NPAD * K2PAD];
__device__ __align__(16) __half g_gates[(size_t)M_ROWS * N3H];   // fp16 gates
__device__ float g_acc[B_SZ * H_DIM];

// ---------------------------------------------------------------------------
__device__ __forceinline__ uint32_t smem_u32(const void* p) {
    uint32_t a;
    asm("{ .reg .u64 t; cvta.to.shared.u64 t, %1; cvt.u32.u64 %0, t; }" : "=r"(a) : "l"(p));
    return a;
}
__device__ __forceinline__ float sigmoid_f(float x) {
    return __fdividef(1.0f, 1.0f + __expf(-x));
}
__device__ __forceinline__ float tanh_fast(float x) {
    return 1.0f - __fdividef(2.0f, __expf(2.0f * x) + 1.0f);
}

#define CP_ASYNC16(dst, src) \
    asm volatile("cp.async.cg.shared.global [%0], [%1], 16;" :: "r"(dst), "l"(src) : "memory")
#define CP_COMMIT() asm volatile("cp.async.commit_group;" ::: "memory")
#define CP_WAIT(n)  asm volatile("cp.async.wait_group %0;" :: "n"(n) : "memory")

#define LDSM_X4(r0, r1, r2, r3, addr) \
    asm volatile("ldmatrix.sync.aligned.m8n8.x4.shared.b16 {%0,%1,%2,%3}, [%4];" \
                 : "=r"(r0), "=r"(r1), "=r"(r2), "=r"(r3) : "r"(addr))

#define MMA_FP16(d, a, b0, b1) \
    asm volatile("mma.sync.aligned.m16n8k16.row.col.f32.f16.f16.f32 " \
                 "{%0,%1,%2,%3}, {%4,%5,%6,%7}, {%8,%9}, {%0,%1,%2,%3};" \
                 : "+f"((d)[0]), "+f"((d)[1]), "+f"((d)[2]), "+f"((d)[3]) \
                 : "r"((a)[0]), "r"((a)[1]), "r"((a)[2]), "r"((a)[3]), "r"(b0), "r"(b1))

// ---------------------------------------------------------------------------
// fp32 -> fp16 conversions, vectorized
// ---------------------------------------------------------------------------
__global__ void cvt_W_kernel(const float* __restrict__ in, int K4, int Kpad, int which) {
    __half* w = (which == 0) ? g_W1 : (which == 1) ? g_W2 : g_W3;
    const int r = blockIdx.x;
    const float4* row = (const float4*)(in + (size_t)r * (K4 * 4));
    for (int k4 = threadIdx.x; k4 < K4; k4 += blockDim.x) {
        const float4 x = row[k4];
        __half2 h01 = __floats2half2_rn(x.x, x.y);
        __half2 h23 = __floats2half2_rn(x.z, x.w);
        uint2 ph;
        ph.x = *(uint32_t*)&h01; ph.y = *(uint32_t*)&h23;
        *(uint2*)(w + (size_t)r * Kpad + k4 * 4) = ph;
    }
}

__global__ void cvt_A1_kernel(const float* __restrict__ sent) {
    const int r = blockIdx.x;
    const float4* row = (const float4*)(sent + (size_t)r * E_DIM);
    for (int k4 = threadIdx.x; k4 < E_DIM / 4; k4 += blockDim.x) {
        const float4 x = row[k4];
        __half2 h01 = __floats2half2_rn(x.x, x.y);
        __half2 h23 = __floats2half2_rn(x.z, x.w);
        uint2 ph;
        ph.x = *(uint32_t*)&h01; ph.y = *(uint32_t*)&h23;
        *(uint2*)(g_A1 + (size_t)r * K1PAD + k4 * 4) = ph;
    }
}

// ---------------------------------------------------------------------------
// fp16 HMMA GEMM (fp32 accum): g_gates[m,n] = act( A[m,:].W[n,:] + bias[n] )
// Single-sync 4-stage cp.async pipeline, 2 CTAs/SM.
// ---------------------------------------------------------------------------
__global__ __launch_bounds__(256, 2) void gemm_tc(int layer, const float* __restrict__ bias) {
    const __half *A, *W;
    int Kpad;
    if (layer == 1)      { A = g_A1; W = g_W1; Kpad = K1PAD; }
    else if (layer == 2) { A = g_Ax; W = g_W2; Kpad = K2PAD; }
    else                 { A = g_Ax; W = g_W3; Kpad = K2PAD; }
    const int NT = Kpad / BK;

    // m-strip swizzle for L2 reuse: strips of 8 m-groups, n fastest
    const int bx = blockIdx.x;
    const int strip = bx / (8 * 57);
    const int rem   = bx % (8 * 57);
    const int mg    = strip * 8 + (rem % 8);
    const int ng    = rem / 8;
    const int m0 = mg * BM;
    const int n0 = ng * BN;

    extern __shared__ char smem_raw[];
    const uint32_t sbase = smem_u32(smem_raw);

    const int tid = threadIdx.x;
    const int wid = tid >> 5;
    const int lid = tid & 31;
    const int wm = (wid & 1) * 64;
    const int wn = (wid >> 1) * 32;

    auto load_chunk = [&](int t, int slot) {
        const uint32_t st = sbase + (uint32_t)slot * STAGE_BYTES;
        const int kc = t * BK;
#pragma unroll
        for (int i = 0; i < 2; i++) {
            const int u = tid + i * 256;          // 0..511
            const int r = u >> 2, c = u & 3;
            const uint32_t so = (uint32_t)(r * ROWB + c * 16);
            CP_ASYNC16(st + OFF_A + so, A + (size_t)(m0 + r) * Kpad + kc + c * 8);
            CP_ASYNC16(st + OFF_B + so, W + (size_t)(n0 + r) * Kpad + kc + c * 8);
        }
        CP_COMMIT();
    };

    float d[4][4][4];
#pragma unroll
    for (int mi = 0; mi < 4; mi++)
#pragma unroll
        for (int ni = 0; ni < 4; ni++)
#pragma unroll
            for (int q = 0; q < 4; q++) d[mi][ni][q] = 0.0f;

    const uint32_t a_row = (uint32_t)(wm + (lid & 15));
    const uint32_t a_kb  = (uint32_t)((lid >> 4) * 16);
    const uint32_t b_row = (uint32_t)(wn + (lid & 7) + ((lid >> 4) & 1) * 8);
    const uint32_t b_kb  = (uint32_t)(((lid >> 3) & 1) * 16);

    // Prologue: fill 3 of 4 stages
    load_chunk(0, 0);
    load_chunk(1, 1);
    load_chunk(2, 2);

    for (int t = 0; t < NT; ++t) {
        CP_WAIT(2);            // oldest of 3 outstanding (chunk t) has landed
        __syncthreads();       // visibility of chunk t + retire slot of chunk t-1

        // Refill the slot that compute(t-1) just finished with
        if (t + 3 < NT) load_chunk(t + 3, (t + 3) % NSTAGE);
        else CP_COMMIT();      // keep outstanding-group count uniform

        const uint32_t st = sbase + (uint32_t)(t % NSTAGE) * STAGE_BYTES;
#pragma unroll
        for (int ks = 0; ks < 2; ks++) {
            const uint32_t kbyte = (uint32_t)(ks * 32);
            uint32_t af[4][4];
#pragma unroll
            for (int mi = 0; mi < 4; mi++) {
                const uint32_t ra = st + (a_row + mi * 16) * ROWB + kbyte + a_kb;
                LDSM_X4(af[mi][0], af[mi][1], af[mi][2], af[mi][3], ra + OFF_A);
            }
            uint32_t bf[4][2];
#pragma unroll
            for (int j = 0; j < 2; j++) {
                const uint32_t rb = st + (b_row + j * 16) * ROWB + kbyte + b_kb;
                LDSM_X4(bf[2*j][0], bf[2*j][1], bf[2*j+1][0], bf[2*j+1][1], rb + OFF_B);
            }
#pragma unroll
            for (int mi = 0; mi < 4; mi++)
#pragma unroll
                for (int ni = 0; ni < 4; ni++)
                    MMA_FP16(d[mi][ni], af[mi], bf[ni][0], bf[ni][1]);
        }
    }

    __syncthreads();

    // Epilogue: bias + activation + fp16 store
    const int er = lid >> 2;
    const int ec = (lid & 3) * 2;
#pragma unroll
    for (int mi = 0; mi < 4; mi++) {
#pragma unroll
        for (int ni = 0; ni < 4; ni++) {
            const int n = n0 + wn + ni * 8 + ec;     // even; H_DIM even -> no straddle
            if (n >= N3H) continue;
            const int m = m0 + wm + mi * 16 + er;
            const float2 bs = *(const float2*)(bias + n);
            const bool tA = (n < H_DIM);
            {
                const float y0 = d[mi][ni][0] + bs.x;
                const float y1 = d[mi][ni][1] + bs.y;
                const float v0 = tA ? tanh_fast(y0) : sigmoid_f(y0);
                const float v1 = tA ? tanh_fast(y1) : sigmoid_f(y1);
                *(__half2*)(g_gates + (size_t)m * N3H + n) = __floats2half2_rn(v0, v1);
            }
            {
                const float y0 = d[mi][ni][2] + bs.x;
                const float y1 = d[mi][ni][3] + bs.y;
                const float v0 = tA ? tanh_fast(y0) : sigmoid_f(y0);
                const float v1 = tA ? tanh_fast(y1) : sigmoid_f(y1);
                *(__half2*)(g_gates + (size_t)(m + 8) * N3H + n) = __floats2half2_rn(v0, v1);
            }
        }
    }
}

// ---------------------------------------------------------------------------
// fo-pool scan: 4 h-lanes/thread, fp16 gate reads, fp32 recurrence.
// ---------------------------------------------------------------------------
__device__ __forceinline__ float4 ld_gates4(const __half* p) {
    const uint2 u = *(const uint2*)p;
    const float2 a = __half22float2(*(const __half2*)&u.x);
    const float2 b = __half22float2(*(const __half2*)&u.y);
    return make_float4(a.x, a.y, b.x, b.y);
}

__global__ void scan_kernel(int mode, const int* __restrict__ sent_len,
                            float* __restrict__ out)
{
    const int tix = blockIdx.x * blockDim.x + threadIdx.x;
    if (tix >= (B_SZ * H_DIM) / 4) return;
    const int flat = tix * 4;
    const int b = flat / H_DIM;
    const int h = flat - b * H_DIM;

    const size_t stride = (size_t)B_SZ * N3H;
    size_t base = (size_t)b * N3H + h;

    float4 c = make_float4(0.f, 0.f, 0.f, 0.f);

    if (mode != 2) {
        size_t xbase = (size_t)b * K2PAD + h;
        const size_t xstride = (size_t)B_SZ * K2PAD;
#pragma unroll 4
        for (int s = 0; s < S_LEN; ++s) {
            const float4 z = ld_gates4(g_gates + base);
            const float4 f = ld_gates4(g_gates + base + H_DIM);
            const float4 o = ld_gates4(g_gates + base + 2 * H_DIM);
            c.x = fmaf(f.x, c.x - z.x, z.x);
            c.y = fmaf(f.y, c.y - z.y, z.y);
            c.z = fmaf(f.z, c.z - z.z, z.z);
            c.w = fmaf(f.w, c.w - z.w, z.w);
            __half2 h01 = __floats2half2_rn(o.x * c.x, o.y * c.y);
            __half2 h23 = __floats2half2_rn(o.z * c.z, o.w * c.w);
            uint2 pk;
            pk.x = *(uint32_t*)&h01;
            pk.y = *(uint32_t*)&h23;
            *(uint2*)(g_Ax + xbase) = pk;
            base  += stride;
            xbase += xstride;
        }
    } else {
#pragma unroll 4
        for (int s = 0; s < S_LEN; ++s) {
            const float4 z = ld_gates4(g_gates + base);
            const float4 f = ld_gates4(g_gates + base + H_DIM);
            c.x = fmaf(f.x, c.x - z.x, z.x);
            c.y = fmaf(f.y, c.y - z.y, z.y);
            c.z = fmaf(f.z, c.z - z.z, z.z);
            c.w = fmaf(f.w, c.w - z.w, z.w);
            base += stride;
        }
    }

    if (mode == 0) {
        *(float4*)(g_acc + flat) = c;
    } else if (mode == 1) {
        float4 a = *(const float4*)(g_acc + flat);
        a.x += c.x; a.y += c.y; a.z += c.z; a.w += c.w;
        *(float4*)(g_acc + flat) = a;
    } else {
        const float inv = 1.0f / (float)sent_len[b];
        float4 a = *(const float4*)(g_acc + flat);
        float4 v;
        v.x = (a.x + c.x) * inv;
        v.y = (a.y + c.y) * inv;
        v.z = (a.z + c.z) * inv;
        v.w = (a.w + c.w) * inv;
        *(float4*)(out + flat) = v;
    }
}

// ---------------------------------------------------------------------------
extern "C" void kernel_launch(void* const* d_in, const int* in_sizes, int n_in,
                              void* d_out, int out_size)
{
    const float* sent     = (const float*)d_in[0];
    const int*   sent_len = (const int*)  d_in[1];
    const float* W1 = (const float*)d_in[2];
    const float* b1 = (const float*)d_in[3];
    const float* W2 = (const float*)d_in[4];
    const float* b2 = (const float*)d_in[5];
    const float* W3 = (const float*)d_in[6];
    const float* b3 = (const float*)d_in[7];
    float* out = (float*)d_out;

    cudaFuncSetAttribute(gemm_tc, cudaFuncAttributeMaxDynamicSharedMemorySize, GEMM_SMEM_BYTES);

    cvt_W_kernel<<<N3H, 128>>>(W1, E_DIM / 4, K1PAD, 0);
    cvt_W_kernel<<<N3H, 128>>>(W2, H_DIM / 4, K2PAD, 1);
    cvt_W_kernel<<<N3H, 128>>>(W3, H_DIM / 4, K2PAD, 2);
    cvt_A1_kernel<<<M_ROWS, 64>>>(sent);

    const int nblocks = (M_ROWS / BM) * (NPAD / BN);      // 64 * 57 = 3648
    const int sblocks = ((B_SZ * H_DIM) / 4 + 127) / 128; // 150

    gemm_tc<<<nblocks, 256, GEMM_SMEM_BYTES>>>(1, b1);
    scan_kernel<<<sblocks, 128>>>(0, sent_len, out);

    gemm_tc<<<nblocks, 256, GEMM_SMEM_BYTES>>>(2, b2);
    scan_kernel<<<sblocks, 128>>>(1, sent_len, out);

    gemm_tc<<<nblocks, 256, GEMM_SMEM_BYTES>>>(3, b3);
    scan_kernel<<<sblocks, 128>>>(2, sent_len, out);
}